// round 3
// baseline (speedup 1.0000x reference)
#include <cuda_runtime.h>
#include <cuda_bf16.h>
#include <cstdint>

// ---------------- problem constants ----------------
#define L_SEQ   4096      // F*P = 16*256
#define DM      1024
#define DI      2048
#define DSTATE  16
#define DTRANK  64
#define XDBL_W  96        // DTRANK + 2*DSTATE
#define HID     4096
#define NCHUNK  16
#define CHUNKL  256       // L_SEQ / NCHUNK
#define POOLED  256       // 16 * 4 * 4

// ---------------- scratch (device globals; no cudaMalloc allowed) ----------------
__device__ float g_ln   [L_SEQ * DM];          // layernorm output
__device__ float g_xz   [L_SEQ * 2 * DI];      // in_proj output [L, 4096]
__device__ float g_u    [L_SEQ * DI];          // conv+silu output
__device__ float g_xdbl [L_SEQ * XDBL_W];      // x_proj output
__device__ float g_dt   [L_SEQ * DI];          // softplus(dt)
__device__ float g_y    [L_SEQ * DI];          // gated scan output
__device__ float g_mamba[L_SEQ * DM];          // residual + out_proj
__device__ float g_ln2  [L_SEQ * DM];          // final layernorm
__device__ float g_pool [POOLED * DM];
__device__ float g_mid  [POOLED * HID];
__device__ float g_A2   [DI * DSTATE];         // A * log2(e)
__device__ float g_Ap   [NCHUNK * DI * DSTATE];
__device__ float g_Be   [NCHUNK * DI * DSTATE];
__device__ float g_hin  [NCHUNK * DI * DSTATE];

// ---------------- helpers ----------------
__device__ __forceinline__ float siluf(float x) {
    return x / (1.f + __expf(-x));
}
__device__ __forceinline__ float softplusf(float x) {
    return (x > 20.f) ? x : log1pf(__expf(x));
}
__device__ __forceinline__ float gelu_exact(float x) {
    return 0.5f * x * (1.f + erff(x * 0.70710678118654752440f));
}

// ---------------- layernorm: one block per row ----------------
__global__ void layernorm_k(const float* __restrict__ x, float* __restrict__ o,
                            const float* __restrict__ w, const float* __restrict__ b,
                            int cols) {
    int row = blockIdx.x;
    const float* xr = x + (size_t)row * cols;
    float s = 0.f, s2 = 0.f;
    for (int c = threadIdx.x; c < cols; c += blockDim.x) {
        float v = xr[c];
        s += v; s2 += v * v;
    }
    __shared__ float shs[8], shs2[8], shmu, shinv;
    for (int off = 16; off; off >>= 1) {
        s  += __shfl_down_sync(0xffffffffu, s,  off);
        s2 += __shfl_down_sync(0xffffffffu, s2, off);
    }
    int wid = threadIdx.x >> 5, lid = threadIdx.x & 31;
    if (!lid) { shs[wid] = s; shs2[wid] = s2; }
    __syncthreads();
    if (threadIdx.x == 0) {
        float ts = 0.f, ts2 = 0.f;
        int nw = blockDim.x >> 5;
        for (int i = 0; i < nw; ++i) { ts += shs[i]; ts2 += shs2[i]; }
        float mu = ts / cols;
        float var = ts2 / cols - mu * mu;
        shmu = mu;
        shinv = rsqrtf(var + 1e-5f);
    }
    __syncthreads();
    float mu = shmu, inv = shinv;
    float* orow = o + (size_t)row * cols;
    for (int c = threadIdx.x; c < cols; c += blockDim.x) {
        orow[c] = (xr[c] - mu) * inv * w[c] + b[c];
    }
}

// ---------------- generic register-blocked fp32 GEMM ----------------
// C[M,N] = epilogue(A[M,K] @ B[K,N])
// EPI: 0 none, 1 bias+softplus, 2 +residual, 3 bias+gelu, 4 bias
template<int BM, int BN, int BK, int TM, int TN, int EPI>
__global__ void gemm_k(const float* __restrict__ A, int lda,
                       const float* __restrict__ B, int ldb,
                       float* __restrict__ C, int ldc,
                       const float* __restrict__ bias,
                       const float* __restrict__ res, int ldres,
                       int M, int N, int K) {
    constexpr int THREADS = (BM / TM) * (BN / TN);   // 256
    __shared__ float As[BK][BM + 4];
    __shared__ float Bs[BK][BN];
    const int tid  = threadIdx.x;
    const int tRow = tid / (BN / TN);
    const int tCol = tid % (BN / TN);
    const int rowBase = blockIdx.y * BM + tRow * TM;
    const int colBase = blockIdx.x * BN + tCol * TN;

    float acc[TM][TN];
    #pragma unroll
    for (int i = 0; i < TM; ++i)
        #pragma unroll
        for (int j = 0; j < TN; ++j) acc[i][j] = 0.f;

    for (int k0 = 0; k0 < K; k0 += BK) {
        // load A tile (transposed into smem)
        #pragma unroll
        for (int p = 0; p < (BM * BK) / THREADS; ++p) {
            int idx = p * THREADS + tid;
            int m = idx / BK, kk = idx % BK;
            int gr = blockIdx.y * BM + m;
            As[kk][m] = (gr < M) ? A[(size_t)gr * lda + k0 + kk] : 0.f;
        }
        // load B tile
        #pragma unroll
        for (int p = 0; p < (BK * BN) / THREADS; ++p) {
            int idx = p * THREADS + tid;
            int kk = idx / BN, c = idx % BN;
            int gc = blockIdx.x * BN + c;
            Bs[kk][c] = (gc < N) ? B[(size_t)(k0 + kk) * ldb + gc] : 0.f;
        }
        __syncthreads();
        #pragma unroll
        for (int kk = 0; kk < BK; ++kk) {
            float af[TM], bf[TN];
            #pragma unroll
            for (int i = 0; i < TM; ++i) af[i] = As[kk][tRow * TM + i];
            #pragma unroll
            for (int j = 0; j < TN; ++j) bf[j] = Bs[kk][tCol * TN + j];
            #pragma unroll
            for (int i = 0; i < TM; ++i)
                #pragma unroll
                for (int j = 0; j < TN; ++j)
                    acc[i][j] = fmaf(af[i], bf[j], acc[i][j]);
        }
        __syncthreads();
    }

    #pragma unroll
    for (int i = 0; i < TM; ++i) {
        int row = rowBase + i;
        if (row >= M) continue;
        #pragma unroll
        for (int j = 0; j < TN; ++j) {
            int col = colBase + j;
            if (col >= N) continue;
            float v = acc[i][j];
            if (EPI == 1) v = softplusf(v + bias[col]);
            else if (EPI == 2) v += res[(size_t)row * ldres + col];
            else if (EPI == 3) v = gelu_exact(v + bias[col]);
            else if (EPI == 4) v += bias[col];
            C[(size_t)row * ldc + col] = v;
        }
    }
}

// ---------------- depthwise causal conv (k=4) + silu ----------------
__global__ void conv_silu_k(const float* __restrict__ xz, const float* __restrict__ w,
                            const float* __restrict__ b, float* __restrict__ u) {
    int t = blockIdx.x * blockDim.x + threadIdx.x;
    if (t >= L_SEQ * DI) return;
    int l = t >> 11;           // /2048
    int c = t & (DI - 1);
    float acc = b[c];
    #pragma unroll
    for (int k = 0; k < 4; ++k) {
        int ls = l - 3 + k;
        if (ls >= 0) acc = fmaf(w[c * 4 + k], xz[(size_t)ls * (2 * DI) + c], acc);
    }
    u[t] = siluf(acc);
}

// ---------------- A2 = -exp(A_log) * log2(e) ----------------
__global__ void a2_k(const float* __restrict__ A_log, float* __restrict__ A2) {
    int t = blockIdx.x * blockDim.x + threadIdx.x;
    if (t < DI * DSTATE) A2[t] = -__expf(A_log[t]) * 1.44269504088896f;
}

// ---------------- scan pass 1: per-chunk affine summaries ----------------
// thread t -> (chunk, n, d); computes h_end (with h_in = 0) and prod(a)
__global__ void scan1_k(const float* __restrict__ dt, const float* __restrict__ u,
                        const float* __restrict__ xdbl, const float* __restrict__ A2,
                        float* __restrict__ Ap, float* __restrict__ Be) {
    int t = blockIdx.x * blockDim.x + threadIdx.x;
    if (t >= NCHUNK * DI * DSTATE) return;
    int chunk = t >> 15;               // / 32768
    int r = t & 32767;
    int n = r >> 11;                   // / 2048
    int d = r & (DI - 1);
    float a2 = A2[d * DSTATE + n];
    float h = 0.f, ap = 1.f;
    int l0 = chunk * CHUNKL;
    for (int s = 0; s < CHUNKL; ++s) {
        int l = l0 + s;
        float dtv = dt[(size_t)l * DI + d];
        float uv  = u [(size_t)l * DI + d];
        float bv  = xdbl[l * XDBL_W + DTRANK + n];
        float a = exp2f(dtv * a2);
        h = fmaf(a, h, dtv * uv * bv);
        ap *= a;
    }
    Ap[t] = ap;
    Be[t] = h;
}

// ---------------- scan pass 2: inter-chunk sequential scan (16 steps) ----------------
__global__ void scan2_k(const float* __restrict__ Ap, const float* __restrict__ Be,
                        float* __restrict__ hin) {
    int t = blockIdx.x * blockDim.x + threadIdx.x;
    if (t >= DI * DSTATE) return;
    float h = 0.f;
    #pragma unroll
    for (int c = 0; c < NCHUNK; ++c) {
        hin[c * (DI * DSTATE) + t] = h;
        h = fmaf(Ap[c * (DI * DSTATE) + t], h, Be[c * (DI * DSTATE) + t]);
    }
}

// ---------------- scan pass 3: recompute with h_in, fuse y, D-skip, silu(z) gate ----------------
// thread t -> (chunk, d) with h[16] in registers
__global__ void scan3_k(const float* __restrict__ dt, const float* __restrict__ u,
                        const float* __restrict__ xdbl, const float* __restrict__ A2,
                        const float* __restrict__ hin, const float* __restrict__ Dp,
                        const float* __restrict__ xz, float* __restrict__ y) {
    int t = blockIdx.x * blockDim.x + threadIdx.x;
    if (t >= NCHUNK * DI) return;
    int chunk = t >> 11;
    int d = t & (DI - 1);
    float h[DSTATE], a2[DSTATE];
    #pragma unroll
    for (int n = 0; n < DSTATE; ++n) {
        h[n]  = hin[chunk * (DI * DSTATE) + n * DI + d];
        a2[n] = A2[d * DSTATE + n];
    }
    float Dd = Dp[d];
    int l0 = chunk * CHUNKL;
    for (int s = 0; s < CHUNKL; ++s) {
        int l = l0 + s;
        float dtv = dt[(size_t)l * DI + d];
        float uv  = u [(size_t)l * DI + d];
        float du  = dtv * uv;
        float acc = 0.f;
        #pragma unroll
        for (int n = 0; n < DSTATE; ++n) {
            float a = exp2f(dtv * a2[n]);
            h[n] = fmaf(a, h[n], du * xdbl[l * XDBL_W + DTRANK + n]);
            acc  = fmaf(h[n], xdbl[l * XDBL_W + DTRANK + DSTATE + n], acc);
        }
        acc = fmaf(uv, Dd, acc);
        float zv = xz[(size_t)l * (2 * DI) + DI + d];
        y[(size_t)l * DI + d] = acc * siluf(zv);
    }
}

// ---------------- avg pool 4x4 over (h,w) ----------------
__global__ void pool_k(const float* __restrict__ x, float* __restrict__ o) {
    int t = blockIdx.x * blockDim.x + threadIdx.x;
    if (t >= POOLED * DM) return;
    int d = t & (DM - 1);
    int po = t >> 10;
    int f = po >> 4, hh = (po >> 2) & 3, ww = po & 3;
    float s = 0.f;
    #pragma unroll
    for (int i = 0; i < 4; ++i)
        #pragma unroll
        for (int j = 0; j < 4; ++j) {
            int l = f * 256 + (hh * 4 + i) * 16 + (ww * 4 + j);
            s += x[(size_t)l * DM + d];
        }
    o[t] = s * 0.0625f;
}

// ---------------- launch ----------------
extern "C" void kernel_launch(void* const* d_in, const int* in_sizes, int n_in,
                              void* d_out, int out_size) {
    const float* vst        = (const float*)d_in[0];
    const float* ln_w       = (const float*)d_in[1];
    const float* ln_b       = (const float*)d_in[2];
    const float* in_proj_w  = (const float*)d_in[3];
    const float* conv_w     = (const float*)d_in[4];
    const float* conv_b     = (const float*)d_in[5];
    const float* x_proj_w   = (const float*)d_in[6];
    const float* dt_proj_w  = (const float*)d_in[7];
    const float* dt_proj_b  = (const float*)d_in[8];
    const float* A_log      = (const float*)d_in[9];
    const float* D_param    = (const float*)d_in[10];
    const float* out_proj_w = (const float*)d_in[11];
    const float* fln_w      = (const float*)d_in[12];
    const float* fln_b      = (const float*)d_in[13];
    const float* mlp_w1     = (const float*)d_in[14];
    const float* mlp_b1     = (const float*)d_in[15];
    const float* mlp_w2     = (const float*)d_in[16];
    const float* mlp_b2     = (const float*)d_in[17];
    float* out = (float*)d_out;

    float *p_ln, *p_xz, *p_u, *p_xdbl, *p_dt, *p_y, *p_mamba, *p_ln2,
          *p_pool, *p_mid, *p_A2, *p_Ap, *p_Be, *p_hin;
    cudaGetSymbolAddress((void**)&p_ln,    g_ln);
    cudaGetSymbolAddress((void**)&p_xz,    g_xz);
    cudaGetSymbolAddress((void**)&p_u,     g_u);
    cudaGetSymbolAddress((void**)&p_xdbl,  g_xdbl);
    cudaGetSymbolAddress((void**)&p_dt,    g_dt);
    cudaGetSymbolAddress((void**)&p_y,     g_y);
    cudaGetSymbolAddress((void**)&p_mamba, g_mamba);
    cudaGetSymbolAddress((void**)&p_ln2,   g_ln2);
    cudaGetSymbolAddress((void**)&p_pool,  g_pool);
    cudaGetSymbolAddress((void**)&p_mid,   g_mid);
    cudaGetSymbolAddress((void**)&p_A2,    g_A2);
    cudaGetSymbolAddress((void**)&p_Ap,    g_Ap);
    cudaGetSymbolAddress((void**)&p_Be,    g_Be);
    cudaGetSymbolAddress((void**)&p_hin,   g_hin);

    // 1. layernorm
    layernorm_k<<<L_SEQ, 256>>>(vst, p_ln, ln_w, ln_b, DM);

    // 2. in_proj: [4096,1024] @ [1024,4096]
    gemm_k<128,128,16,8,8,0><<<dim3(4096/128, 4096/128), 256>>>(
        p_ln, DM, in_proj_w, 2*DI, p_xz, 2*DI, nullptr, nullptr, 0,
        L_SEQ, 2*DI, DM);

    // 3. depthwise conv + silu
    conv_silu_k<<<(L_SEQ * DI) / 256, 256>>>(p_xz, conv_w, conv_b, p_u);

    // 4. x_proj: [4096,2048] @ [2048,96]
    gemm_k<64,32,16,4,2,0><<<dim3((XDBL_W + 31)/32, L_SEQ/64), 256>>>(
        p_u, DI, x_proj_w, XDBL_W, p_xdbl, XDBL_W, nullptr, nullptr, 0,
        L_SEQ, XDBL_W, DI);

    // 5. dt_proj + softplus: [4096,64] @ [64,2048]
    gemm_k<128,128,16,8,8,1><<<dim3(DI/128, L_SEQ/128), 256>>>(
        p_xdbl, XDBL_W, dt_proj_w, DI, p_dt, DI, dt_proj_b, nullptr, 0,
        L_SEQ, DI, DTRANK);

    // 6. selective scan (3-pass chunked)
    a2_k<<<(DI * DSTATE) / 256, 256>>>(A_log, p_A2);
    scan1_k<<<(NCHUNK * DI * DSTATE) / 256, 256>>>(p_dt, p_u, p_xdbl, p_A2, p_Ap, p_Be);
    scan2_k<<<(DI * DSTATE) / 256, 256>>>(p_Ap, p_Be, p_hin);
    scan3_k<<<(NCHUNK * DI) / 256, 256>>>(p_dt, p_u, p_xdbl, p_A2, p_hin, D_param, p_xz, p_y);

    // 7. out_proj + residual: [4096,2048] @ [2048,1024] + vst
    gemm_k<128,128,16,8,8,2><<<dim3(DM/128, L_SEQ/128), 256>>>(
        p_y, DI, out_proj_w, DM, p_mamba, DM, nullptr, vst, DM,
        L_SEQ, DM, DI);

    // 8. final layernorm
    layernorm_k<<<L_SEQ, 256>>>(p_mamba, p_ln2, fln_w, fln_b, DM);

    // 9. avg pool 4x4
    pool_k<<<(POOLED * DM) / 256, 256>>>(p_ln2, p_pool);

    // 10. mlp1 + bias + exact gelu: [256,1024] @ [1024,4096]
    gemm_k<64,128,16,4,8,3><<<dim3(HID/128, POOLED/64), 256>>>(
        p_pool, DM, mlp_w1, HID, p_mid, HID, mlp_b1, nullptr, 0,
        POOLED, HID, DM);

    // 11. mlp2 + bias: [256,4096] @ [4096,4096]
    gemm_k<64,128,16,4,8,4><<<dim3(HID/128, POOLED/64), 256>>>(
        p_mid, HID, mlp_w2, HID, out, HID, mlp_b2, nullptr, 0,
        POOLED, HID, HID);
}

// round 4
// speedup vs baseline: 1.5235x; 1.5235x over previous
#include <cuda_runtime.h>
#include <cuda_bf16.h>
#include <cstdint>

// ---------------- problem constants ----------------
#define L_SEQ   4096      // F*P = 16*256
#define DM      1024
#define DI      2048
#define DSTATE  16
#define DTRANK  64
#define XDBL_W  96        // DTRANK + 2*DSTATE
#define HID     4096
#define NCHUNK  16
#define CHUNKL  256       // L_SEQ / NCHUNK
#define POOLED  256       // 16 * 4 * 4

// ---------------- scratch (device globals; no cudaMalloc allowed) ----------------
__device__ float g_ln   [L_SEQ * DM];
__device__ float g_xz   [L_SEQ * 2 * DI];
__device__ float g_u    [L_SEQ * DI];
__device__ float g_xdbl [L_SEQ * XDBL_W];
__device__ float g_dt   [L_SEQ * DI];
__device__ float g_y    [L_SEQ * DI];
__device__ float g_mamba[L_SEQ * DM];
__device__ float g_ln2  [L_SEQ * DM];
__device__ float g_pool [POOLED * DM];
__device__ float g_mid  [POOLED * HID];
__device__ float g_A2   [DI * DSTATE];
__device__ float g_Ap   [NCHUNK * DI * DSTATE];
__device__ float g_Be   [NCHUNK * DI * DSTATE];
__device__ float g_hin  [NCHUNK * DI * DSTATE];
__device__ float g_part [8 * POOLED * HID];    // split-K partials (max 8x256x4096)

// ---------------- helpers ----------------
__device__ __forceinline__ float siluf(float x) {
    return x / (1.f + __expf(-x));
}
__device__ __forceinline__ float softplusf(float x) {
    return (x > 20.f) ? x : log1pf(__expf(x));
}
__device__ __forceinline__ float gelu_exact(float x) {
    return 0.5f * x * (1.f + erff(x * 0.70710678118654752440f));
}

// ---------------- layernorm: one block per row ----------------
__global__ void layernorm_k(const float* __restrict__ x, float* __restrict__ o,
                            const float* __restrict__ w, const float* __restrict__ b,
                            int cols) {
    int row = blockIdx.x;
    const float* xr = x + (size_t)row * cols;
    float s = 0.f, s2 = 0.f;
    for (int c = threadIdx.x; c < cols; c += blockDim.x) {
        float v = xr[c];
        s += v; s2 += v * v;
    }
    __shared__ float shs[8], shs2[8], shmu, shinv;
    for (int off = 16; off; off >>= 1) {
        s  += __shfl_down_sync(0xffffffffu, s,  off);
        s2 += __shfl_down_sync(0xffffffffu, s2, off);
    }
    int wid = threadIdx.x >> 5, lid = threadIdx.x & 31;
    if (!lid) { shs[wid] = s; shs2[wid] = s2; }
    __syncthreads();
    if (threadIdx.x == 0) {
        float ts = 0.f, ts2 = 0.f;
        int nw = blockDim.x >> 5;
        for (int i = 0; i < nw; ++i) { ts += shs[i]; ts2 += shs2[i]; }
        float mu = ts / cols;
        float var = ts2 / cols - mu * mu;
        shmu = mu;
        shinv = rsqrtf(var + 1e-5f);
    }
    __syncthreads();
    float mu = shmu, inv = shinv;
    float* orow = o + (size_t)row * cols;
    for (int c = threadIdx.x; c < cols; c += blockDim.x) {
        orow[c] = (xr[c] - mu) * inv * w[c] + b[c];
    }
}

// ---------------- tf32 tensor-core GEMM (3xTF32 compensated) ----------------
// C[M,N] = epilogue(A[M,K] @ B[K,N]); row-major A, B.
// Block tile 128x128x32, 512 threads = 16 warps (4x4), warp tile 32x32.
// If gridDim.z > 1: split-K, write raw partials to Cpart (ldc = N).
// EPI: 0 none, 1 bias+softplus, 2 +residual, 3 bias+gelu, 4 bias

__device__ __forceinline__ void mma_tf32(float* c, const uint32_t* a, const uint32_t* b) {
    asm volatile(
        "mma.sync.aligned.m16n8k8.row.col.f32.tf32.tf32.f32 "
        "{%0,%1,%2,%3}, {%4,%5,%6,%7}, {%8,%9}, {%0,%1,%2,%3};\n"
        : "+f"(c[0]), "+f"(c[1]), "+f"(c[2]), "+f"(c[3])
        : "r"(a[0]), "r"(a[1]), "r"(a[2]), "r"(a[3]), "r"(b[0]), "r"(b[1]));
}

template<int EPI>
__device__ __forceinline__ float epi_apply(float v, int r, int c,
                                           const float* bias,
                                           const float* res, int ldres) {
    if (EPI == 1) return softplusf(v + bias[c]);
    if (EPI == 2) return v + res[(size_t)r * ldres + c];
    if (EPI == 3) return gelu_exact(v + bias[c]);
    if (EPI == 4) return v + bias[c];
    return v;
}

template<int EPI>
__global__ __launch_bounds__(512, 1)
void gemm_tf32_k(const float* __restrict__ A, int lda,
                 const float* __restrict__ B, int ldb,
                 float* __restrict__ C, int ldc,
                 float* __restrict__ Cpart,
                 const float* __restrict__ bias,
                 const float* __restrict__ res, int ldres,
                 int M, int N, int K) {
    __shared__ float As[32][132];   // [k][m]
    __shared__ float Bs[32][132];   // [k][n]
    const int tid  = threadIdx.x;
    const int warp = tid >> 5;
    const int lane = tid & 31;
    const int grp  = lane >> 2;     // 0..7
    const int tig  = lane & 3;      // 0..3
    const int wm   = warp >> 2;     // 0..3
    const int wn   = warp & 3;      // 0..3
    const int row0 = blockIdx.y * 128;
    const int col0 = blockIdx.x * 128;
    const int kLen = K / gridDim.z;
    const int kBeg = blockIdx.z * kLen;

    float acc[2][4][4];
    #pragma unroll
    for (int i = 0; i < 2; ++i)
        #pragma unroll
        for (int j = 0; j < 4; ++j)
            #pragma unroll
            for (int q = 0; q < 4; ++q) acc[i][j][q] = 0.f;

    for (int k0 = kBeg; k0 < kBeg + kLen; k0 += 32) {
        // A tile -> As[k][m] (transpose)
        #pragma unroll
        for (int p = 0; p < 2; ++p) {
            int idx = p * 512 + tid;       // 0..1023
            int m   = idx >> 3;            // 0..127
            int kq  = idx & 7;             // 0..7 -> k = kq*4..+3
            const float4 v = *reinterpret_cast<const float4*>(
                A + (size_t)(row0 + m) * lda + k0 + kq * 4);
            As[kq * 4 + 0][m] = v.x;
            As[kq * 4 + 1][m] = v.y;
            As[kq * 4 + 2][m] = v.z;
            As[kq * 4 + 3][m] = v.w;
        }
        // B tile -> Bs[k][n]
        #pragma unroll
        for (int p = 0; p < 2; ++p) {
            int idx = p * 512 + tid;
            int kk  = idx >> 5;            // 0..31
            int nq  = idx & 31;            // 0..31 -> n = nq*4..+3
            int gc  = col0 + nq * 4;
            float4 v;
            if (gc + 3 < N) {
                v = *reinterpret_cast<const float4*>(B + (size_t)(k0 + kk) * ldb + gc);
            } else {
                v.x = (gc + 0 < N) ? B[(size_t)(k0 + kk) * ldb + gc + 0] : 0.f;
                v.y = (gc + 1 < N) ? B[(size_t)(k0 + kk) * ldb + gc + 1] : 0.f;
                v.z = (gc + 2 < N) ? B[(size_t)(k0 + kk) * ldb + gc + 2] : 0.f;
                v.w = (gc + 3 < N) ? B[(size_t)(k0 + kk) * ldb + gc + 3] : 0.f;
            }
            *reinterpret_cast<float4*>(&Bs[kk][nq * 4]) = v;
        }
        __syncthreads();

        #pragma unroll
        for (int ks = 0; ks < 32; ks += 8) {
            uint32_t ahi[2][4], alo[2][4], bhi[4][2], blo[4][2];
            #pragma unroll
            for (int i = 0; i < 2; ++i) {
                int m = wm * 32 + i * 16;
                float f0 = As[ks + tig    ][m + grp];       // A[grp   ][tig]
                float f1 = As[ks + tig    ][m + grp + 8];   // A[grp+8 ][tig]
                float f2 = As[ks + tig + 4][m + grp];       // A[grp   ][tig+4]
                float f3 = As[ks + tig + 4][m + grp + 8];   // A[grp+8 ][tig+4]
                uint32_t h;
                h = __float_as_uint(f0) & 0xFFFFE000u; ahi[i][0] = h; alo[i][0] = __float_as_uint(f0 - __uint_as_float(h));
                h = __float_as_uint(f1) & 0xFFFFE000u; ahi[i][1] = h; alo[i][1] = __float_as_uint(f1 - __uint_as_float(h));
                h = __float_as_uint(f2) & 0xFFFFE000u; ahi[i][2] = h; alo[i][2] = __float_as_uint(f2 - __uint_as_float(h));
                h = __float_as_uint(f3) & 0xFFFFE000u; ahi[i][3] = h; alo[i][3] = __float_as_uint(f3 - __uint_as_float(h));
            }
            #pragma unroll
            for (int j = 0; j < 4; ++j) {
                int n = wn * 32 + j * 8 + grp;
                float g0 = Bs[ks + tig    ][n];             // B[tig  ][grp]
                float g1 = Bs[ks + tig + 4][n];             // B[tig+4][grp]
                uint32_t h;
                h = __float_as_uint(g0) & 0xFFFFE000u; bhi[j][0] = h; blo[j][0] = __float_as_uint(g0 - __uint_as_float(h));
                h = __float_as_uint(g1) & 0xFFFFE000u; bhi[j][1] = h; blo[j][1] = __float_as_uint(g1 - __uint_as_float(h));
            }
            #pragma unroll
            for (int i = 0; i < 2; ++i)
                #pragma unroll
                for (int j = 0; j < 4; ++j) {
                    mma_tf32(acc[i][j], ahi[i], bhi[j]);
                    mma_tf32(acc[i][j], ahi[i], blo[j]);
                    mma_tf32(acc[i][j], alo[i], bhi[j]);
                }
        }
        __syncthreads();
    }

    // -------- write out --------
    if (gridDim.z > 1) {
        float* P = Cpart + (size_t)blockIdx.z * M * N;
        #pragma unroll
        for (int i = 0; i < 2; ++i)
            #pragma unroll
            for (int j = 0; j < 4; ++j) {
                int r = row0 + wm * 32 + i * 16 + grp;
                int c = col0 + wn * 32 + j * 8 + tig * 2;
                if (c < N) {
                    P[(size_t)r * N + c]       = acc[i][j][0];
                    P[(size_t)(r + 8) * N + c] = acc[i][j][2];
                }
                if (c + 1 < N) {
                    P[(size_t)r * N + c + 1]       = acc[i][j][1];
                    P[(size_t)(r + 8) * N + c + 1] = acc[i][j][3];
                }
            }
    } else {
        #pragma unroll
        for (int i = 0; i < 2; ++i)
            #pragma unroll
            for (int j = 0; j < 4; ++j) {
                int r = row0 + wm * 32 + i * 16 + grp;
                int c = col0 + wn * 32 + j * 8 + tig * 2;
                if (c < N) {
                    C[(size_t)r * ldc + c]       = epi_apply<EPI>(acc[i][j][0], r,     c,     bias, res, ldres);
                    C[(size_t)(r + 8) * ldc + c] = epi_apply<EPI>(acc[i][j][2], r + 8, c,     bias, res, ldres);
                }
                if (c + 1 < N) {
                    C[(size_t)r * ldc + c + 1]       = epi_apply<EPI>(acc[i][j][1], r,     c + 1, bias, res, ldres);
                    C[(size_t)(r + 8) * ldc + c + 1] = epi_apply<EPI>(acc[i][j][3], r + 8, c + 1, bias, res, ldres);
                }
            }
    }
}

// ---------------- split-K reduction with epilogue ----------------
template<int EPI>
__global__ void reduceK_k(const float* __restrict__ part, int S, int MN, int N,
                          const float* __restrict__ bias, float* __restrict__ out) {
    int idx = blockIdx.x * blockDim.x + threadIdx.x;
    if (idx >= MN) return;
    float s = 0.f;
    for (int z = 0; z < S; ++z) s += part[(size_t)z * MN + idx];
    int c = idx % N;
    if (EPI == 3) s = gelu_exact(s + bias[c]);
    else if (EPI == 4) s += bias[c];
    out[idx] = s;
}

// ---------------- depthwise causal conv (k=4) + silu ----------------
__global__ void conv_silu_k(const float* __restrict__ xz, const float* __restrict__ w,
                            const float* __restrict__ b, float* __restrict__ u) {
    int t = blockIdx.x * blockDim.x + threadIdx.x;
    if (t >= L_SEQ * DI) return;
    int l = t >> 11;
    int c = t & (DI - 1);
    float acc = b[c];
    #pragma unroll
    for (int k = 0; k < 4; ++k) {
        int ls = l - 3 + k;
        if (ls >= 0) acc = fmaf(w[c * 4 + k], xz[(size_t)ls * (2 * DI) + c], acc);
    }
    u[t] = siluf(acc);
}

// ---------------- A2 = -exp(A_log) * log2(e) ----------------
__global__ void a2_k(const float* __restrict__ A_log, float* __restrict__ A2) {
    int t = blockIdx.x * blockDim.x + threadIdx.x;
    if (t < DI * DSTATE) A2[t] = -__expf(A_log[t]) * 1.44269504088896f;
}

// ---------------- scan pass 1: per-chunk affine summaries ----------------
__global__ void scan1_k(const float* __restrict__ dt, const float* __restrict__ u,
                        const float* __restrict__ xdbl, const float* __restrict__ A2,
                        float* __restrict__ Ap, float* __restrict__ Be) {
    int t = blockIdx.x * blockDim.x + threadIdx.x;
    if (t >= NCHUNK * DI * DSTATE) return;
    int chunk = t >> 15;
    int r = t & 32767;
    int n = r >> 11;
    int d = r & (DI - 1);
    float a2 = A2[d * DSTATE + n];
    float h = 0.f, ap = 1.f;
    int l0 = chunk * CHUNKL;
    for (int s = 0; s < CHUNKL; ++s) {
        int l = l0 + s;
        float dtv = dt[(size_t)l * DI + d];
        float uv  = u [(size_t)l * DI + d];
        float bv  = xdbl[l * XDBL_W + DTRANK + n];
        float a = exp2f(dtv * a2);
        h = fmaf(a, h, dtv * uv * bv);
        ap *= a;
    }
    Ap[t] = ap;
    Be[t] = h;
}

// ---------------- scan pass 2: inter-chunk sequential scan ----------------
__global__ void scan2_k(const float* __restrict__ Ap, const float* __restrict__ Be,
                        float* __restrict__ hin) {
    int t = blockIdx.x * blockDim.x + threadIdx.x;
    if (t >= DI * DSTATE) return;
    float h = 0.f;
    #pragma unroll
    for (int c = 0; c < NCHUNK; ++c) {
        hin[c * (DI * DSTATE) + t] = h;
        h = fmaf(Ap[c * (DI * DSTATE) + t], h, Be[c * (DI * DSTATE) + t]);
    }
}

// ---------------- scan pass 3: recompute with h_in, fuse y, D-skip, gate ----------------
__global__ void scan3_k(const float* __restrict__ dt, const float* __restrict__ u,
                        const float* __restrict__ xdbl, const float* __restrict__ A2,
                        const float* __restrict__ hin, const float* __restrict__ Dp,
                        const float* __restrict__ xz, float* __restrict__ y) {
    int t = blockIdx.x * blockDim.x + threadIdx.x;
    if (t >= NCHUNK * DI) return;
    int chunk = t >> 11;
    int d = t & (DI - 1);
    float h[DSTATE], a2[DSTATE];
    #pragma unroll
    for (int n = 0; n < DSTATE; ++n) {
        h[n]  = hin[chunk * (DI * DSTATE) + n * DI + d];
        a2[n] = A2[d * DSTATE + n];
    }
    float Dd = Dp[d];
    int l0 = chunk * CHUNKL;
    for (int s = 0; s < CHUNKL; ++s) {
        int l = l0 + s;
        float dtv = dt[(size_t)l * DI + d];
        float uv  = u [(size_t)l * DI + d];
        float du  = dtv * uv;
        float acc = 0.f;
        #pragma unroll
        for (int n = 0; n < DSTATE; ++n) {
            float a = exp2f(dtv * a2[n]);
            h[n] = fmaf(a, h[n], du * xdbl[l * XDBL_W + DTRANK + n]);
            acc  = fmaf(h[n], xdbl[l * XDBL_W + DTRANK + DSTATE + n], acc);
        }
        acc = fmaf(uv, Dd, acc);
        float zv = xz[(size_t)l * (2 * DI) + DI + d];
        y[(size_t)l * DI + d] = acc * siluf(zv);
    }
}

// ---------------- avg pool 4x4 over (h,w) ----------------
__global__ void pool_k(const float* __restrict__ x, float* __restrict__ o) {
    int t = blockIdx.x * blockDim.x + threadIdx.x;
    if (t >= POOLED * DM) return;
    int d = t & (DM - 1);
    int po = t >> 10;
    int f = po >> 4, hh = (po >> 2) & 3, ww = po & 3;
    float s = 0.f;
    #pragma unroll
    for (int i = 0; i < 4; ++i)
        #pragma unroll
        for (int j = 0; j < 4; ++j) {
            int l = f * 256 + (hh * 4 + i) * 16 + (ww * 4 + j);
            s += x[(size_t)l * DM + d];
        }
    o[t] = s * 0.0625f;
}

// ---------------- launch ----------------
extern "C" void kernel_launch(void* const* d_in, const int* in_sizes, int n_in,
                              void* d_out, int out_size) {
    const float* vst        = (const float*)d_in[0];
    const float* ln_w       = (const float*)d_in[1];
    const float* ln_b       = (const float*)d_in[2];
    const float* in_proj_w  = (const float*)d_in[3];
    const float* conv_w     = (const float*)d_in[4];
    const float* conv_b     = (const float*)d_in[5];
    const float* x_proj_w   = (const float*)d_in[6];
    const float* dt_proj_w  = (const float*)d_in[7];
    const float* dt_proj_b  = (const float*)d_in[8];
    const float* A_log      = (const float*)d_in[9];
    const float* D_param    = (const float*)d_in[10];
    const float* out_proj_w = (const float*)d_in[11];
    const float* fln_w      = (const float*)d_in[12];
    const float* fln_b      = (const float*)d_in[13];
    const float* mlp_w1     = (const float*)d_in[14];
    const float* mlp_b1     = (const float*)d_in[15];
    const float* mlp_w2     = (const float*)d_in[16];
    const float* mlp_b2     = (const float*)d_in[17];
    float* out = (float*)d_out;

    float *p_ln, *p_xz, *p_u, *p_xdbl, *p_dt, *p_y, *p_mamba, *p_ln2,
          *p_pool, *p_mid, *p_A2, *p_Ap, *p_Be, *p_hin, *p_part;
    cudaGetSymbolAddress((void**)&p_ln,    g_ln);
    cudaGetSymbolAddress((void**)&p_xz,    g_xz);
    cudaGetSymbolAddress((void**)&p_u,     g_u);
    cudaGetSymbolAddress((void**)&p_xdbl,  g_xdbl);
    cudaGetSymbolAddress((void**)&p_dt,    g_dt);
    cudaGetSymbolAddress((void**)&p_y,     g_y);
    cudaGetSymbolAddress((void**)&p_mamba, g_mamba);
    cudaGetSymbolAddress((void**)&p_ln2,   g_ln2);
    cudaGetSymbolAddress((void**)&p_pool,  g_pool);
    cudaGetSymbolAddress((void**)&p_mid,   g_mid);
    cudaGetSymbolAddress((void**)&p_A2,    g_A2);
    cudaGetSymbolAddress((void**)&p_Ap,    g_Ap);
    cudaGetSymbolAddress((void**)&p_Be,    g_Be);
    cudaGetSymbolAddress((void**)&p_hin,   g_hin);
    cudaGetSymbolAddress((void**)&p_part,  g_part);

    // 1. layernorm
    layernorm_k<<<L_SEQ, 256>>>(vst, p_ln, ln_w, ln_b, DM);

    // 2. in_proj: [4096,1024] @ [1024,4096]
    gemm_tf32_k<0><<<dim3(32, 32, 1), 512>>>(
        p_ln, DM, in_proj_w, 2*DI, p_xz, 2*DI, nullptr, nullptr, nullptr, 0,
        L_SEQ, 2*DI, DM);

    // 3. depthwise conv + silu
    conv_silu_k<<<(L_SEQ * DI) / 256, 256>>>(p_xz, conv_w, conv_b, p_u);

    // 4. x_proj: [4096,2048] @ [2048,96], split-K=8
    gemm_tf32_k<0><<<dim3(1, 32, 8), 512>>>(
        p_u, DI, x_proj_w, XDBL_W, nullptr, 0, p_part, nullptr, nullptr, 0,
        L_SEQ, XDBL_W, DI);
    reduceK_k<0><<<(L_SEQ * XDBL_W + 255) / 256, 256>>>(
        p_part, 8, L_SEQ * XDBL_W, XDBL_W, nullptr, p_xdbl);

    // 5. dt_proj + softplus: [4096,64] @ [64,2048]
    gemm_tf32_k<1><<<dim3(16, 32, 1), 512>>>(
        p_xdbl, XDBL_W, dt_proj_w, DI, p_dt, DI, nullptr, dt_proj_b, nullptr, 0,
        L_SEQ, DI, DTRANK);

    // 6. selective scan (3-pass chunked)
    a2_k<<<(DI * DSTATE) / 256, 256>>>(A_log, p_A2);
    scan1_k<<<(NCHUNK * DI * DSTATE) / 256, 256>>>(p_dt, p_u, p_xdbl, p_A2, p_Ap, p_Be);
    scan2_k<<<(DI * DSTATE) / 256, 256>>>(p_Ap, p_Be, p_hin);
    scan3_k<<<(NCHUNK * DI) / 256, 256>>>(p_dt, p_u, p_xdbl, p_A2, p_hin, D_param, p_xz, p_y);

    // 7. out_proj + residual: [4096,2048] @ [2048,1024] + vst
    gemm_tf32_k<2><<<dim3(8, 32, 1), 512>>>(
        p_y, DI, out_proj_w, DM, p_mamba, DM, nullptr, nullptr, vst, DM,
        L_SEQ, DM, DI);

    // 8. final layernorm
    layernorm_k<<<L_SEQ, 256>>>(p_mamba, p_ln2, fln_w, fln_b, DM);

    // 9. avg pool 4x4
    pool_k<<<(POOLED * DM) / 256, 256>>>(p_ln2, p_pool);

    // 10. mlp1: [256,1024] @ [1024,4096], split-K=4, gelu+bias epilogue in reduce
    gemm_tf32_k<0><<<dim3(32, 2, 4), 512>>>(
        p_pool, DM, mlp_w1, HID, nullptr, 0, p_part, nullptr, nullptr, 0,
        POOLED, HID, DM);
    reduceK_k<3><<<(POOLED * HID + 255) / 256, 256>>>(
        p_part, 4, POOLED * HID, HID, mlp_b1, p_mid);

    // 11. mlp2: [256,4096] @ [4096,4096], split-K=8, bias epilogue in reduce
    gemm_tf32_k<0><<<dim3(32, 2, 8), 512>>>(
        p_mid, HID, mlp_w2, HID, nullptr, 0, p_part, nullptr, nullptr, 0,
        POOLED, HID, HID);
    reduceK_k<4><<<(POOLED * HID + 255) / 256, 256>>>(
        p_part, 8, POOLED * HID, HID, mlp_b2, out);
}

// round 5
// speedup vs baseline: 1.8321x; 1.2026x over previous
#include <cuda_runtime.h>
#include <cuda_bf16.h>
#include <cstdint>

// ---------------- problem constants ----------------
#define L_SEQ   4096      // F*P = 16*256
#define DM      1024
#define DI      2048
#define DSTATE  16
#define DTRANK  64
#define XDBL_W  96        // DTRANK + 2*DSTATE
#define HID     4096
#define NCHUNK  16
#define CHUNKL  256       // L_SEQ / NCHUNK
#define POOLED  256       // 16 * 4 * 4

// smem geometry for the pipelined GEMM
#define A_PAD   36        // floats per As row (BK=32 + 4)
#define B_PAD   136       // floats per Bs row (BN=128 + 8)
#define A_STG   (128 * A_PAD)          // 4608 floats
#define B_STG   (32 * B_PAD)           // 4352 floats
#define STG_FLOATS (A_STG + B_STG)     // 8960
#define SMEM_DYN_BYTES (2 * STG_FLOATS * 4)  // 71680

// ---------------- scratch (device globals; no cudaMalloc allowed) ----------------
__device__ float g_ln   [L_SEQ * DM];
__device__ float g_xz   [L_SEQ * 2 * DI];
__device__ float g_u    [L_SEQ * DI];
__device__ float g_xdbl [L_SEQ * XDBL_W];
__device__ float g_dt   [L_SEQ * DI];
__device__ float g_y    [L_SEQ * DI];
__device__ float g_mamba[L_SEQ * DM];
__device__ float g_ln2  [L_SEQ * DM];
__device__ float g_pool [POOLED * DM];
__device__ float g_mid  [POOLED * HID];
__device__ float g_A2   [DI * DSTATE];
__device__ float g_Ap   [NCHUNK * DI * DSTATE];
__device__ float g_Be   [NCHUNK * DI * DSTATE];
__device__ float g_hin  [NCHUNK * DI * DSTATE];
__device__ float g_part [8 * POOLED * HID];    // split-K partials (max 8x256x4096)

// ---------------- helpers ----------------
__device__ __forceinline__ float siluf(float x) {
    return x / (1.f + __expf(-x));
}
__device__ __forceinline__ float softplusf(float x) {
    return (x > 20.f) ? x : log1pf(__expf(x));
}
__device__ __forceinline__ float gelu_exact(float x) {
    return 0.5f * x * (1.f + erff(x * 0.70710678118654752440f));
}

__device__ __forceinline__ void cp_async16(float* dst_smem, const float* src_gmem, bool pred) {
    uint32_t d = (uint32_t)__cvta_generic_to_shared(dst_smem);
    int sz = pred ? 16 : 0;
    asm volatile("cp.async.cg.shared.global [%0], [%1], 16, %2;\n"
                 :: "r"(d), "l"(src_gmem), "r"(sz));
}
__device__ __forceinline__ void cp_commit() {
    asm volatile("cp.async.commit_group;\n");
}
template<int N>
__device__ __forceinline__ void cp_wait() {
    asm volatile("cp.async.wait_group %0;\n" :: "n"(N));
}

// ---------------- layernorm: one block per row ----------------
__global__ void layernorm_k(const float* __restrict__ x, float* __restrict__ o,
                            const float* __restrict__ w, const float* __restrict__ b,
                            int cols) {
    int row = blockIdx.x;
    const float* xr = x + (size_t)row * cols;
    float s = 0.f, s2 = 0.f;
    for (int c = threadIdx.x; c < cols; c += blockDim.x) {
        float v = xr[c];
        s += v; s2 += v * v;
    }
    __shared__ float shs[8], shs2[8], shmu, shinv;
    for (int off = 16; off; off >>= 1) {
        s  += __shfl_down_sync(0xffffffffu, s,  off);
        s2 += __shfl_down_sync(0xffffffffu, s2, off);
    }
    int wid = threadIdx.x >> 5, lid = threadIdx.x & 31;
    if (!lid) { shs[wid] = s; shs2[wid] = s2; }
    __syncthreads();
    if (threadIdx.x == 0) {
        float ts = 0.f, ts2 = 0.f;
        int nw = blockDim.x >> 5;
        for (int i = 0; i < nw; ++i) { ts += shs[i]; ts2 += shs2[i]; }
        float mu = ts / cols;
        float var = ts2 / cols - mu * mu;
        shmu = mu;
        shinv = rsqrtf(var + 1e-5f);
    }
    __syncthreads();
    float mu = shmu, inv = shinv;
    float* orow = o + (size_t)row * cols;
    for (int c = threadIdx.x; c < cols; c += blockDim.x) {
        orow[c] = (xr[c] - mu) * inv * w[c] + b[c];
    }
}

// ---------------- tf32 tensor-core GEMM (3xTF32, cp.async double-buffered) ----------------
// C[M,N] = epilogue(A[M,K] @ B[K,N]); row-major A, B.
// Block tile 128x128x32, 512 threads = 16 warps (4x4), warp tile 32x32.
// If gridDim.z > 1: split-K, write raw partials to Cpart.
// EPI: 0 none, 1 bias+softplus, 2 +residual, 3 bias+gelu, 4 bias

__device__ __forceinline__ void mma_tf32(float* c, const uint32_t* a, const uint32_t* b) {
    asm volatile(
        "mma.sync.aligned.m16n8k8.row.col.f32.tf32.tf32.f32 "
        "{%0,%1,%2,%3}, {%4,%5,%6,%7}, {%8,%9}, {%0,%1,%2,%3};\n"
        : "+f"(c[0]), "+f"(c[1]), "+f"(c[2]), "+f"(c[3])
        : "r"(a[0]), "r"(a[1]), "r"(a[2]), "r"(a[3]), "r"(b[0]), "r"(b[1]));
}

template<int EPI>
__device__ __forceinline__ float epi_apply(float v, int r, int c,
                                           const float* bias,
                                           const float* res, int ldres) {
    if (EPI == 1) return softplusf(v + bias[c]);
    if (EPI == 2) return v + res[(size_t)r * ldres + c];
    if (EPI == 3) return gelu_exact(v + bias[c]);
    if (EPI == 4) return v + bias[c];
    return v;
}

template<int EPI>
__global__ __launch_bounds__(512, 1)
void gemm_tf32_k(const float* __restrict__ A, int lda,
                 const float* __restrict__ B, int ldb,
                 float* __restrict__ C, int ldc,
                 float* __restrict__ Cpart,
                 const float* __restrict__ bias,
                 const float* __restrict__ res, int ldres,
                 int M, int N, int K) {
    extern __shared__ float sm[];
    const int tid  = threadIdx.x;
    const int warp = tid >> 5;
    const int lane = tid & 31;
    const int grp  = lane >> 2;     // 0..7
    const int tig  = lane & 3;      // 0..3
    const int wm   = warp >> 2;     // 0..3
    const int wn   = warp & 3;      // 0..3
    const int row0 = blockIdx.y * 128;
    const int col0 = blockIdx.x * 128;
    const int kLen = K / gridDim.z;
    const int kBeg = blockIdx.z * kLen;
    const int nK   = kLen / 32;

    // per-thread load coordinates (2 float4 each for A and B)
    const int a_m0  = tid >> 3,  a_kq = tid & 7;          // p=0
    const int a_m1  = (512 + tid) >> 3, a_kq1 = tid & 7;  // p=1 (same kq)
    const int b_kk0 = tid >> 5,  b_nq0 = tid & 31;
    const int b_kk1 = (512 + tid) >> 5, b_nq1 = tid & 31;

    float acc[2][4][4];
    #pragma unroll
    for (int i = 0; i < 2; ++i)
        #pragma unroll
        for (int j = 0; j < 4; ++j)
            #pragma unroll
            for (int q = 0; q < 4; ++q) acc[i][j][q] = 0.f;

    auto issue_tile = [&](int stage, int k0) {
        float* AsS = sm + stage * STG_FLOATS;
        float* BsS = AsS + A_STG;
        cp_async16(AsS + a_m0 * A_PAD + a_kq * 4,
                   A + (size_t)(row0 + a_m0) * lda + k0 + a_kq * 4, true);
        cp_async16(AsS + a_m1 * A_PAD + a_kq1 * 4,
                   A + (size_t)(row0 + a_m1) * lda + k0 + a_kq1 * 4, true);
        int gc0 = col0 + b_nq0 * 4;
        int gc1 = col0 + b_nq1 * 4;
        cp_async16(BsS + b_kk0 * B_PAD + b_nq0 * 4,
                   B + (size_t)(k0 + b_kk0) * ldb + gc0, gc0 + 3 < N);
        cp_async16(BsS + b_kk1 * B_PAD + b_nq1 * 4,
                   B + (size_t)(k0 + b_kk1) * ldb + gc1, gc1 + 3 < N);
        cp_commit();
    };

    issue_tile(0, kBeg);

    for (int kt = 0; kt < nK; ++kt) {
        if (kt + 1 < nK) {
            issue_tile((kt + 1) & 1, kBeg + (kt + 1) * 32);
            cp_wait<1>();
        } else {
            cp_wait<0>();
        }
        __syncthreads();

        const float* AsS = sm + (kt & 1) * STG_FLOATS;
        const float* BsS = AsS + A_STG;

        #pragma unroll
        for (int ks = 0; ks < 32; ks += 8) {
            uint32_t ahi[2][4], alo[2][4], bhi[4][2], blo[4][2];
            #pragma unroll
            for (int i = 0; i < 2; ++i) {
                int m = wm * 32 + i * 16;
                float f0 = AsS[(m + grp    ) * A_PAD + ks + tig    ];
                float f1 = AsS[(m + grp + 8) * A_PAD + ks + tig    ];
                float f2 = AsS[(m + grp    ) * A_PAD + ks + tig + 4];
                float f3 = AsS[(m + grp + 8) * A_PAD + ks + tig + 4];
                uint32_t h;
                h = __float_as_uint(f0) & 0xFFFFE000u; ahi[i][0] = h; alo[i][0] = __float_as_uint(f0 - __uint_as_float(h));
                h = __float_as_uint(f1) & 0xFFFFE000u; ahi[i][1] = h; alo[i][1] = __float_as_uint(f1 - __uint_as_float(h));
                h = __float_as_uint(f2) & 0xFFFFE000u; ahi[i][2] = h; alo[i][2] = __float_as_uint(f2 - __uint_as_float(h));
                h = __float_as_uint(f3) & 0xFFFFE000u; ahi[i][3] = h; alo[i][3] = __float_as_uint(f3 - __uint_as_float(h));
            }
            #pragma unroll
            for (int j = 0; j < 4; ++j) {
                int n = wn * 32 + j * 8 + grp;
                float g0 = BsS[(ks + tig    ) * B_PAD + n];
                float g1 = BsS[(ks + tig + 4) * B_PAD + n];
                uint32_t h;
                h = __float_as_uint(g0) & 0xFFFFE000u; bhi[j][0] = h; blo[j][0] = __float_as_uint(g0 - __uint_as_float(h));
                h = __float_as_uint(g1) & 0xFFFFE000u; bhi[j][1] = h; blo[j][1] = __float_as_uint(g1 - __uint_as_float(h));
            }
            #pragma unroll
            for (int i = 0; i < 2; ++i)
                #pragma unroll
                for (int j = 0; j < 4; ++j) {
                    mma_tf32(acc[i][j], ahi[i], bhi[j]);
                    mma_tf32(acc[i][j], ahi[i], blo[j]);
                    mma_tf32(acc[i][j], alo[i], bhi[j]);
                }
        }
        __syncthreads();
    }

    // -------- write out --------
    if (gridDim.z > 1) {
        float* P = Cpart + (size_t)blockIdx.z * M * N;
        #pragma unroll
        for (int i = 0; i < 2; ++i)
            #pragma unroll
            for (int j = 0; j < 4; ++j) {
                int r = row0 + wm * 32 + i * 16 + grp;
                int c = col0 + wn * 32 + j * 8 + tig * 2;
                if (c < N) {
                    P[(size_t)r * N + c]       = acc[i][j][0];
                    P[(size_t)(r + 8) * N + c] = acc[i][j][2];
                }
                if (c + 1 < N) {
                    P[(size_t)r * N + c + 1]       = acc[i][j][1];
                    P[(size_t)(r + 8) * N + c + 1] = acc[i][j][3];
                }
            }
    } else {
        #pragma unroll
        for (int i = 0; i < 2; ++i)
            #pragma unroll
            for (int j = 0; j < 4; ++j) {
                int r = row0 + wm * 32 + i * 16 + grp;
                int c = col0 + wn * 32 + j * 8 + tig * 2;
                if (c < N) {
                    C[(size_t)r * ldc + c]       = epi_apply<EPI>(acc[i][j][0], r,     c,     bias, res, ldres);
                    C[(size_t)(r + 8) * ldc + c] = epi_apply<EPI>(acc[i][j][2], r + 8, c,     bias, res, ldres);
                }
                if (c + 1 < N) {
                    C[(size_t)r * ldc + c + 1]       = epi_apply<EPI>(acc[i][j][1], r,     c + 1, bias, res, ldres);
                    C[(size_t)(r + 8) * ldc + c + 1] = epi_apply<EPI>(acc[i][j][3], r + 8, c + 1, bias, res, ldres);
                }
            }
    }
}

// ---------------- split-K reduction with epilogue (float4) ----------------
template<int EPI>
__global__ void reduceK_k(const float* __restrict__ part, int S, int MN, int N,
                          const float* __restrict__ bias, float* __restrict__ out) {
    int idx4 = blockIdx.x * blockDim.x + threadIdx.x;
    if (idx4 * 4 >= MN) return;
    float4 s = make_float4(0.f, 0.f, 0.f, 0.f);
    for (int z = 0; z < S; ++z) {
        float4 v = *reinterpret_cast<const float4*>(part + (size_t)z * MN + idx4 * 4);
        s.x += v.x; s.y += v.y; s.z += v.z; s.w += v.w;
    }
    int c = (idx4 * 4) % N;
    if (EPI == 3) {
        s.x = gelu_exact(s.x + bias[c]);
        s.y = gelu_exact(s.y + bias[c + 1]);
        s.z = gelu_exact(s.z + bias[c + 2]);
        s.w = gelu_exact(s.w + bias[c + 3]);
    } else if (EPI == 4) {
        s.x += bias[c]; s.y += bias[c + 1]; s.z += bias[c + 2]; s.w += bias[c + 3];
    }
    *reinterpret_cast<float4*>(out + (size_t)idx4 * 4) = s;
}

// ---------------- depthwise causal conv (k=4) + silu ----------------
__global__ void conv_silu_k(const float* __restrict__ xz, const float* __restrict__ w,
                            const float* __restrict__ b, float* __restrict__ u) {
    int t = blockIdx.x * blockDim.x + threadIdx.x;
    if (t >= L_SEQ * DI) return;
    int l = t >> 11;
    int c = t & (DI - 1);
    float acc = b[c];
    #pragma unroll
    for (int k = 0; k < 4; ++k) {
        int ls = l - 3 + k;
        if (ls >= 0) acc = fmaf(w[c * 4 + k], xz[(size_t)ls * (2 * DI) + c], acc);
    }
    u[t] = siluf(acc);
}

// ---------------- A2 = -exp(A_log) * log2(e) ----------------
__global__ void a2_k(const float* __restrict__ A_log, float* __restrict__ A2) {
    int t = blockIdx.x * blockDim.x + threadIdx.x;
    if (t < DI * DSTATE) A2[t] = -__expf(A_log[t]) * 1.44269504088896f;
}

// ---------------- scan pass 1: per-chunk affine summaries ----------------
__global__ void scan1_k(const float* __restrict__ dt, const float* __restrict__ u,
                        const float* __restrict__ xdbl, const float* __restrict__ A2,
                        float* __restrict__ Ap, float* __restrict__ Be) {
    int t = blockIdx.x * blockDim.x + threadIdx.x;
    if (t >= NCHUNK * DI * DSTATE) return;
    int chunk = t >> 15;
    int r = t & 32767;
    int n = r >> 11;
    int d = r & (DI - 1);
    float a2 = A2[d * DSTATE + n];
    float h = 0.f, ap = 1.f;
    int l0 = chunk * CHUNKL;
    for (int s = 0; s < CHUNKL; ++s) {
        int l = l0 + s;
        float dtv = dt[(size_t)l * DI + d];
        float uv  = u [(size_t)l * DI + d];
        float bv  = xdbl[l * XDBL_W + DTRANK + n];
        float a = exp2f(dtv * a2);
        h = fmaf(a, h, dtv * uv * bv);
        ap *= a;
    }
    Ap[t] = ap;
    Be[t] = h;
}

// ---------------- scan pass 2: inter-chunk sequential scan ----------------
__global__ void scan2_k(const float* __restrict__ Ap, const float* __restrict__ Be,
                        float* __restrict__ hin) {
    int t = blockIdx.x * blockDim.x + threadIdx.x;
    if (t >= DI * DSTATE) return;
    float h = 0.f;
    #pragma unroll
    for (int c = 0; c < NCHUNK; ++c) {
        hin[c * (DI * DSTATE) + t] = h;
        h = fmaf(Ap[c * (DI * DSTATE) + t], h, Be[c * (DI * DSTATE) + t]);
    }
}

// ---------------- scan pass 3: recompute with h_in, fuse y, D-skip, gate ----------------
__global__ void scan3_k(const float* __restrict__ dt, const float* __restrict__ u,
                        const float* __restrict__ xdbl, const float* __restrict__ A2,
                        const float* __restrict__ hin, const float* __restrict__ Dp,
                        const float* __restrict__ xz, float* __restrict__ y) {
    int t = blockIdx.x * blockDim.x + threadIdx.x;
    if (t >= NCHUNK * DI) return;
    int chunk = t >> 11;
    int d = t & (DI - 1);
    float h[DSTATE], a2[DSTATE];
    #pragma unroll
    for (int n = 0; n < DSTATE; ++n) {
        h[n]  = hin[chunk * (DI * DSTATE) + n * DI + d];
        a2[n] = A2[d * DSTATE + n];
    }
    float Dd = Dp[d];
    int l0 = chunk * CHUNKL;
    for (int s = 0; s < CHUNKL; ++s) {
        int l = l0 + s;
        float dtv = dt[(size_t)l * DI + d];
        float uv  = u [(size_t)l * DI + d];
        float du  = dtv * uv;
        float acc = 0.f;
        #pragma unroll
        for (int n = 0; n < DSTATE; ++n) {
            float a = exp2f(dtv * a2[n]);
            h[n] = fmaf(a, h[n], du * xdbl[l * XDBL_W + DTRANK + n]);
            acc  = fmaf(h[n], xdbl[l * XDBL_W + DTRANK + DSTATE + n], acc);
        }
        acc = fmaf(uv, Dd, acc);
        float zv = xz[(size_t)l * (2 * DI) + DI + d];
        y[(size_t)l * DI + d] = acc * siluf(zv);
    }
}

// ---------------- avg pool 4x4 over (h,w) ----------------
__global__ void pool_k(const float* __restrict__ x, float* __restrict__ o) {
    int t = blockIdx.x * blockDim.x + threadIdx.x;
    if (t >= POOLED * DM) return;
    int d = t & (DM - 1);
    int po = t >> 10;
    int f = po >> 4, hh = (po >> 2) & 3, ww = po & 3;
    float s = 0.f;
    #pragma unroll
    for (int i = 0; i < 4; ++i)
        #pragma unroll
        for (int j = 0; j < 4; ++j) {
            int l = f * 256 + (hh * 4 + i) * 16 + (ww * 4 + j);
            s += x[(size_t)l * DM + d];
        }
    o[t] = s * 0.0625f;
}

// ---------------- launch ----------------
extern "C" void kernel_launch(void* const* d_in, const int* in_sizes, int n_in,
                              void* d_out, int out_size) {
    const float* vst        = (const float*)d_in[0];
    const float* ln_w       = (const float*)d_in[1];
    const float* ln_b       = (const float*)d_in[2];
    const float* in_proj_w  = (const float*)d_in[3];
    const float* conv_w     = (const float*)d_in[4];
    const float* conv_b     = (const float*)d_in[5];
    const float* x_proj_w   = (const float*)d_in[6];
    const float* dt_proj_w  = (const float*)d_in[7];
    const float* dt_proj_b  = (const float*)d_in[8];
    const float* A_log      = (const float*)d_in[9];
    const float* D_param    = (const float*)d_in[10];
    const float* out_proj_w = (const float*)d_in[11];
    const float* fln_w      = (const float*)d_in[12];
    const float* fln_b      = (const float*)d_in[13];
    const float* mlp_w1     = (const float*)d_in[14];
    const float* mlp_b1     = (const float*)d_in[15];
    const float* mlp_w2     = (const float*)d_in[16];
    const float* mlp_b2     = (const float*)d_in[17];
    float* out = (float*)d_out;

    float *p_ln, *p_xz, *p_u, *p_xdbl, *p_dt, *p_y, *p_mamba, *p_ln2,
          *p_pool, *p_mid, *p_A2, *p_Ap, *p_Be, *p_hin, *p_part;
    cudaGetSymbolAddress((void**)&p_ln,    g_ln);
    cudaGetSymbolAddress((void**)&p_xz,    g_xz);
    cudaGetSymbolAddress((void**)&p_u,     g_u);
    cudaGetSymbolAddress((void**)&p_xdbl,  g_xdbl);
    cudaGetSymbolAddress((void**)&p_dt,    g_dt);
    cudaGetSymbolAddress((void**)&p_y,     g_y);
    cudaGetSymbolAddress((void**)&p_mamba, g_mamba);
    cudaGetSymbolAddress((void**)&p_ln2,   g_ln2);
    cudaGetSymbolAddress((void**)&p_pool,  g_pool);
    cudaGetSymbolAddress((void**)&p_mid,   g_mid);
    cudaGetSymbolAddress((void**)&p_A2,    g_A2);
    cudaGetSymbolAddress((void**)&p_Ap,    g_Ap);
    cudaGetSymbolAddress((void**)&p_Be,    g_Be);
    cudaGetSymbolAddress((void**)&p_hin,   g_hin);
    cudaGetSymbolAddress((void**)&p_part,  g_part);

    cudaFuncSetAttribute(gemm_tf32_k<0>, cudaFuncAttributeMaxDynamicSharedMemorySize, SMEM_DYN_BYTES);
    cudaFuncSetAttribute(gemm_tf32_k<1>, cudaFuncAttributeMaxDynamicSharedMemorySize, SMEM_DYN_BYTES);
    cudaFuncSetAttribute(gemm_tf32_k<2>, cudaFuncAttributeMaxDynamicSharedMemorySize, SMEM_DYN_BYTES);

    // 1. layernorm
    layernorm_k<<<L_SEQ, 256>>>(vst, p_ln, ln_w, ln_b, DM);

    // 2. in_proj: [4096,1024] @ [1024,4096]
    gemm_tf32_k<0><<<dim3(32, 32, 1), 512, SMEM_DYN_BYTES>>>(
        p_ln, DM, in_proj_w, 2*DI, p_xz, 2*DI, nullptr, nullptr, nullptr, 0,
        L_SEQ, 2*DI, DM);

    // 3. depthwise conv + silu
    conv_silu_k<<<(L_SEQ * DI) / 256, 256>>>(p_xz, conv_w, conv_b, p_u);

    // 4. x_proj: [4096,2048] @ [2048,96], split-K=8
    gemm_tf32_k<0><<<dim3(1, 32, 8), 512, SMEM_DYN_BYTES>>>(
        p_u, DI, x_proj_w, XDBL_W, nullptr, 0, p_part, nullptr, nullptr, 0,
        L_SEQ, XDBL_W, DI);
    reduceK_k<0><<<(L_SEQ * XDBL_W / 4 + 255) / 256, 256>>>(
        p_part, 8, L_SEQ * XDBL_W, XDBL_W, nullptr, p_xdbl);

    // 5. dt_proj + softplus: [4096,64] @ [64,2048]
    gemm_tf32_k<1><<<dim3(16, 32, 1), 512, SMEM_DYN_BYTES>>>(
        p_xdbl, XDBL_W, dt_proj_w, DI, p_dt, DI, nullptr, dt_proj_b, nullptr, 0,
        L_SEQ, DI, DTRANK);

    // 6. selective scan (3-pass chunked)
    a2_k<<<(DI * DSTATE) / 256, 256>>>(A_log, p_A2);
    scan1_k<<<(NCHUNK * DI * DSTATE) / 256, 256>>>(p_dt, p_u, p_xdbl, p_A2, p_Ap, p_Be);
    scan2_k<<<(DI * DSTATE) / 256, 256>>>(p_Ap, p_Be, p_hin);
    scan3_k<<<(NCHUNK * DI) / 256, 256>>>(p_dt, p_u, p_xdbl, p_A2, p_hin, D_param, p_xz, p_y);

    // 7. out_proj + residual: [4096,2048] @ [2048,1024] + vst
    gemm_tf32_k<2><<<dim3(8, 32, 1), 512, SMEM_DYN_BYTES>>>(
        p_y, DI, out_proj_w, DM, p_mamba, DM, nullptr, nullptr, vst, DM,
        L_SEQ, DM, DI);

    // 8. final layernorm
    layernorm_k<<<L_SEQ, 256>>>(p_mamba, p_ln2, fln_w, fln_b, DM);

    // 9. avg pool 4x4
    pool_k<<<(POOLED * DM) / 256, 256>>>(p_ln2, p_pool);

    // 10. mlp1: [256,1024] @ [1024,4096], split-K=4, gelu+bias epilogue in reduce
    gemm_tf32_k<0><<<dim3(32, 2, 4), 512, SMEM_DYN_BYTES>>>(
        p_pool, DM, mlp_w1, HID, nullptr, 0, p_part, nullptr, nullptr, 0,
        POOLED, HID, DM);
    reduceK_k<3><<<(POOLED * HID / 4 + 255) / 256, 256>>>(
        p_part, 4, POOLED * HID, HID, mlp_b1, p_mid);

    // 11. mlp2: [256,4096] @ [4096,4096], split-K=8, bias epilogue in reduce
    gemm_tf32_k<0><<<dim3(32, 2, 8), 512, SMEM_DYN_BYTES>>>(
        p_mid, HID, mlp_w2, HID, nullptr, 0, p_part, nullptr, nullptr, 0,
        POOLED, HID, HID);
    reduceK_k<4><<<(POOLED * HID / 4 + 255) / 256, 256>>>(
        p_part, 8, POOLED * HID, HID, mlp_b2, out);
}

// round 8
// speedup vs baseline: 2.2128x; 1.2078x over previous
#include <cuda_runtime.h>
#include <cuda_bf16.h>
#include <cstdint>

// ---------------- problem constants ----------------
#define L_SEQ   4096      // F*P = 16*256
#define DM      1024
#define DI      2048
#define DSTATE  16
#define DTRANK  64
#define XDBL_W  96        // DTRANK + 2*DSTATE
#define HID     4096
#define NCHUNK  16
#define CHUNKL  256       // L_SEQ / NCHUNK
#define POOLED  256       // 16 * 4 * 4

// smem geometry for the pipelined GEMM (2 stages, same as round-5 passing kernel)
#define A_PAD   40        // floats per As row (BK=32 + 8) — conflict-free float2 k-pair loads
#define B_PAD   136       // floats per Bs row (BN=128 + 8)
#define A_STG   (128 * A_PAD)          // 5120 floats
#define B_STG   (32 * B_PAD)           // 4352 floats
#define STG_FLOATS (A_STG + B_STG)     // 9472
#define SMEM_DYN_BYTES (2 * STG_FLOATS * 4)  // 75776

// ---------------- scratch (device globals; no cudaMalloc allowed) ----------------
__device__ float g_ln   [L_SEQ * DM];
__device__ float g_xz   [L_SEQ * 2 * DI];
__device__ float g_u    [L_SEQ * DI];
__device__ float g_xdbl [L_SEQ * XDBL_W];
__device__ float g_dt   [L_SEQ * DI];
__device__ float g_y    [L_SEQ * DI];
__device__ float g_mamba[L_SEQ * DM];
__device__ float g_ln2  [L_SEQ * DM];
__device__ float g_pool [POOLED * DM];
__device__ float g_mid  [POOLED * HID];
__device__ float g_A2   [DI * DSTATE];
__device__ float g_Ap   [NCHUNK * DI * DSTATE];
__device__ float g_Be   [NCHUNK * DI * DSTATE];
__device__ float g_hin  [NCHUNK * DI * DSTATE];
__device__ float g_part [8 * POOLED * HID];    // split-K partials (max 8x256x4096)

// ---------------- helpers ----------------
__device__ __forceinline__ float siluf(float x) {
    return x / (1.f + __expf(-x));
}
__device__ __forceinline__ float softplusf(float x) {
    return (x > 20.f) ? x : log1pf(__expf(x));
}
__device__ __forceinline__ float gelu_exact(float x) {
    return 0.5f * x * (1.f + erff(x * 0.70710678118654752440f));
}

__device__ __forceinline__ void cp_async16(float* dst_smem, const float* src_gmem, bool pred) {
    uint32_t d = (uint32_t)__cvta_generic_to_shared(dst_smem);
    int sz = pred ? 16 : 0;
    asm volatile("cp.async.cg.shared.global [%0], [%1], 16, %2;\n"
                 :: "r"(d), "l"(src_gmem), "r"(sz));
}
__device__ __forceinline__ void cp_commit() {
    asm volatile("cp.async.commit_group;\n");
}
template<int N>
__device__ __forceinline__ void cp_wait() {
    asm volatile("cp.async.wait_group %0;\n" :: "n"(N));
}

// split fp32 pair (v0 = even-k, v1 = odd-k) into packed bf16x2 hi and lo parts
__device__ __forceinline__ void bf16split(float v0, float v1, uint32_t& hi, uint32_t& lo) {
    uint32_t h;
    asm("cvt.rn.bf16x2.f32 %0, %1, %2;" : "=r"(h) : "f"(v1), "f"(v0));
    float h0 = __uint_as_float(h << 16);
    float h1 = __uint_as_float(h & 0xFFFF0000u);
    float l0 = v0 - h0;
    float l1 = v1 - h1;
    uint32_t l;
    asm("cvt.rn.bf16x2.f32 %0, %1, %2;" : "=r"(l) : "f"(l1), "f"(l0));
    hi = h; lo = l;
}

// ---------------- layernorm: one block per row ----------------
__global__ void layernorm_k(const float* __restrict__ x, float* __restrict__ o,
                            const float* __restrict__ w, const float* __restrict__ b,
                            int cols) {
    int row = blockIdx.x;
    const float* xr = x + (size_t)row * cols;
    float s = 0.f, s2 = 0.f;
    for (int c = threadIdx.x; c < cols; c += blockDim.x) {
        float v = xr[c];
        s += v; s2 += v * v;
    }
    __shared__ float shs[8], shs2[8], shmu, shinv;
    for (int off = 16; off; off >>= 1) {
        s  += __shfl_down_sync(0xffffffffu, s,  off);
        s2 += __shfl_down_sync(0xffffffffu, s2, off);
    }
    int wid = threadIdx.x >> 5, lid = threadIdx.x & 31;
    if (!lid) { shs[wid] = s; shs2[wid] = s2; }
    __syncthreads();
    if (threadIdx.x == 0) {
        float ts = 0.f, ts2 = 0.f;
        int nw = blockDim.x >> 5;
        for (int i = 0; i < nw; ++i) { ts += shs[i]; ts2 += shs2[i]; }
        float mu = ts / cols;
        float var = ts2 / cols - mu * mu;
        shmu = mu;
        shinv = rsqrtf(var + 1e-5f);
    }
    __syncthreads();
    float mu = shmu, inv = shinv;
    float* orow = o + (size_t)row * cols;
    for (int c = threadIdx.x; c < cols; c += blockDim.x) {
        orow[c] = (xr[c] - mu) * inv * w[c] + b[c];
    }
}

// ---------------- bf16x3 tensor-core GEMM (cp.async double-buffered) ----------------
// C[M,N] = epilogue(A[M,K] @ B[K,N]); row-major A, B.
// Block tile 128x128x32, 512 threads = 16 warps (4x4), warp tile 32x32.
// Math: fp32 = bf16_hi + bf16_lo; C = Ah*Bh + Ah*Bl + Al*Bh via mma.m16n8k16.bf16.
// Control flow identical to the round-5 (passing) 2-stage pipeline.
// If gridDim.z > 1: split-K, write raw partials to Cpart.
// EPI: 0 none, 1 bias+softplus, 2 +residual, 3 bias+gelu, 4 bias

__device__ __forceinline__ void mma_bf16(float* c, const uint32_t* a, const uint32_t* b) {
    asm volatile(
        "mma.sync.aligned.m16n8k16.row.col.f32.bf16.bf16.f32 "
        "{%0,%1,%2,%3}, {%4,%5,%6,%7}, {%8,%9}, {%0,%1,%2,%3};\n"
        : "+f"(c[0]), "+f"(c[1]), "+f"(c[2]), "+f"(c[3])
        : "r"(a[0]), "r"(a[1]), "r"(a[2]), "r"(a[3]), "r"(b[0]), "r"(b[1]));
}

template<int EPI>
__device__ __forceinline__ float epi_apply(float v, int r, int c,
                                           const float* bias,
                                           const float* res, int ldres) {
    if (EPI == 1) return softplusf(v + bias[c]);
    if (EPI == 2) return v + res[(size_t)r * ldres + c];
    if (EPI == 3) return gelu_exact(v + bias[c]);
    if (EPI == 4) return v + bias[c];
    return v;
}

template<int EPI>
__global__ __launch_bounds__(512, 1)
void gemm_bf16x3_k(const float* __restrict__ A, int lda,
                   const float* __restrict__ B, int ldb,
                   float* __restrict__ C, int ldc,
                   float* __restrict__ Cpart,
                   const float* __restrict__ bias,
                   const float* __restrict__ res, int ldres,
                   int M, int N, int K) {
    extern __shared__ float sm[];
    const int tid  = threadIdx.x;
    const int warp = tid >> 5;
    const int lane = tid & 31;
    const int grp  = lane >> 2;     // 0..7
    const int tig  = lane & 3;      // 0..3
    const int wm   = warp >> 2;     // 0..3
    const int wn   = warp & 3;      // 0..3
    const int row0 = blockIdx.y * 128;
    const int col0 = blockIdx.x * 128;
    const int kLen = K / gridDim.z;
    const int kBeg = blockIdx.z * kLen;
    const int nK   = kLen / 32;

    // per-thread load coordinates (2 float4 each for A and B)
    const int a_m0  = tid >> 3,  a_kq = tid & 7;
    const int a_m1  = (512 + tid) >> 3;
    const int b_kk0 = tid >> 5,  b_nq0 = tid & 31;
    const int b_kk1 = (512 + tid) >> 5, b_nq1 = tid & 31;

    float acc[2][4][4];
    #pragma unroll
    for (int i = 0; i < 2; ++i)
        #pragma unroll
        for (int j = 0; j < 4; ++j)
            #pragma unroll
            for (int q = 0; q < 4; ++q) acc[i][j][q] = 0.f;

    auto issue_tile = [&](int stage, int k0) {
        float* AsS = sm + stage * STG_FLOATS;
        float* BsS = AsS + A_STG;
        cp_async16(AsS + a_m0 * A_PAD + a_kq * 4,
                   A + (size_t)(row0 + a_m0) * lda + k0 + a_kq * 4, true);
        cp_async16(AsS + a_m1 * A_PAD + a_kq * 4,
                   A + (size_t)(row0 + a_m1) * lda + k0 + a_kq * 4, true);
        int gc0 = col0 + b_nq0 * 4;
        int gc1 = col0 + b_nq1 * 4;
        cp_async16(BsS + b_kk0 * B_PAD + b_nq0 * 4,
                   B + (size_t)(k0 + b_kk0) * ldb + gc0, gc0 + 3 < N);
        cp_async16(BsS + b_kk1 * B_PAD + b_nq1 * 4,
                   B + (size_t)(k0 + b_kk1) * ldb + gc1, gc1 + 3 < N);
        cp_commit();
    };

    issue_tile(0, kBeg);

    for (int kt = 0; kt < nK; ++kt) {
        if (kt + 1 < nK) {
            issue_tile((kt + 1) & 1, kBeg + (kt + 1) * 32);
            cp_wait<1>();
        } else {
            cp_wait<0>();
        }
        __syncthreads();

        const float* AsS = sm + (kt & 1) * STG_FLOATS;
        const float* BsS = AsS + A_STG;

        #pragma unroll
        for (int ks = 0; ks < 32; ks += 16) {
            uint32_t ahi[2][4], alo[2][4], bhi[4][2], blo[4][2];
            #pragma unroll
            for (int i = 0; i < 2; ++i) {
                int m = wm * 32 + i * 16;
                float2 p0 = *reinterpret_cast<const float2*>(AsS + (m + grp    ) * A_PAD + ks + 2 * tig);
                float2 p1 = *reinterpret_cast<const float2*>(AsS + (m + grp + 8) * A_PAD + ks + 2 * tig);
                float2 p2 = *reinterpret_cast<const float2*>(AsS + (m + grp    ) * A_PAD + ks + 2 * tig + 8);
                float2 p3 = *reinterpret_cast<const float2*>(AsS + (m + grp + 8) * A_PAD + ks + 2 * tig + 8);
                bf16split(p0.x, p0.y, ahi[i][0], alo[i][0]);
                bf16split(p1.x, p1.y, ahi[i][1], alo[i][1]);
                bf16split(p2.x, p2.y, ahi[i][2], alo[i][2]);
                bf16split(p3.x, p3.y, ahi[i][3], alo[i][3]);
            }
            #pragma unroll
            for (int j = 0; j < 4; ++j) {
                int n = wn * 32 + j * 8 + grp;
                float g0 = BsS[(ks + 2 * tig    ) * B_PAD + n];
                float g1 = BsS[(ks + 2 * tig + 1) * B_PAD + n];
                float g2 = BsS[(ks + 2 * tig + 8) * B_PAD + n];
                float g3 = BsS[(ks + 2 * tig + 9) * B_PAD + n];
                bf16split(g0, g1, bhi[j][0], blo[j][0]);
                bf16split(g2, g3, bhi[j][1], blo[j][1]);
            }
            #pragma unroll
            for (int i = 0; i < 2; ++i)
                #pragma unroll
                for (int j = 0; j < 4; ++j) {
                    mma_bf16(acc[i][j], ahi[i], bhi[j]);
                    mma_bf16(acc[i][j], ahi[i], blo[j]);
                    mma_bf16(acc[i][j], alo[i], bhi[j]);
                }
        }
        __syncthreads();
    }

    // -------- write out --------
    if (gridDim.z > 1) {
        float* P = Cpart + (size_t)blockIdx.z * M * N;
        #pragma unroll
        for (int i = 0; i < 2; ++i)
            #pragma unroll
            for (int j = 0; j < 4; ++j) {
                int r = row0 + wm * 32 + i * 16 + grp;
                int c = col0 + wn * 32 + j * 8 + tig * 2;
                if (c < N) {
                    P[(size_t)r * N + c]       = acc[i][j][0];
                    P[(size_t)(r + 8) * N + c] = acc[i][j][2];
                }
                if (c + 1 < N) {
                    P[(size_t)r * N + c + 1]       = acc[i][j][1];
                    P[(size_t)(r + 8) * N + c + 1] = acc[i][j][3];
                }
            }
    } else {
        #pragma unroll
        for (int i = 0; i < 2; ++i)
            #pragma unroll
            for (int j = 0; j < 4; ++j) {
                int r = row0 + wm * 32 + i * 16 + grp;
                int c = col0 + wn * 32 + j * 8 + tig * 2;
                if (c < N) {
                    C[(size_t)r * ldc + c]       = epi_apply<EPI>(acc[i][j][0], r,     c,     bias, res, ldres);
                    C[(size_t)(r + 8) * ldc + c] = epi_apply<EPI>(acc[i][j][2], r + 8, c,     bias, res, ldres);
                }
                if (c + 1 < N) {
                    C[(size_t)r * ldc + c + 1]       = epi_apply<EPI>(acc[i][j][1], r,     c + 1, bias, res, ldres);
                    C[(size_t)(r + 8) * ldc + c + 1] = epi_apply<EPI>(acc[i][j][3], r + 8, c + 1, bias, res, ldres);
                }
            }
    }
}

// ---------------- split-K reduction with epilogue (float4) ----------------
template<int EPI>
__global__ void reduceK_k(const float* __restrict__ part, int S, int MN, int N,
                          const float* __restrict__ bias, float* __restrict__ out) {
    int idx4 = blockIdx.x * blockDim.x + threadIdx.x;
    if (idx4 * 4 >= MN) return;
    float4 s = make_float4(0.f, 0.f, 0.f, 0.f);
    for (int z = 0; z < S; ++z) {
        float4 v = *reinterpret_cast<const float4*>(part + (size_t)z * MN + idx4 * 4);
        s.x += v.x; s.y += v.y; s.z += v.z; s.w += v.w;
    }
    int c = (idx4 * 4) % N;
    if (EPI == 3) {
        s.x = gelu_exact(s.x + bias[c]);
        s.y = gelu_exact(s.y + bias[c + 1]);
        s.z = gelu_exact(s.z + bias[c + 2]);
        s.w = gelu_exact(s.w + bias[c + 3]);
    } else if (EPI == 4) {
        s.x += bias[c]; s.y += bias[c + 1]; s.z += bias[c + 2]; s.w += bias[c + 3];
    }
    *reinterpret_cast<float4*>(out + (size_t)idx4 * 4) = s;
}

// ---------------- depthwise causal conv (k=4) + silu ----------------
__global__ void conv_silu_k(const float* __restrict__ xz, const float* __restrict__ w,
                            const float* __restrict__ b, float* __restrict__ u) {
    int t = blockIdx.x * blockDim.x + threadIdx.x;
    if (t >= L_SEQ * DI) return;
    int l = t >> 11;
    int c = t & (DI - 1);
    float acc = b[c];
    #pragma unroll
    for (int k = 0; k < 4; ++k) {
        int ls = l - 3 + k;
        if (ls >= 0) acc = fmaf(w[c * 4 + k], xz[(size_t)ls * (2 * DI) + c], acc);
    }
    u[t] = siluf(acc);
}

// ---------------- A2 = -exp(A_log) * log2(e) ----------------
__global__ void a2_k(const float* __restrict__ A_log, float* __restrict__ A2) {
    int t = blockIdx.x * blockDim.x + threadIdx.x;
    if (t < DI * DSTATE) A2[t] = -__expf(A_log[t]) * 1.44269504088896f;
}

// ---------------- scan pass 1: per-chunk affine summaries ----------------
__global__ void scan1_k(const float* __restrict__ dt, const float* __restrict__ u,
                        const float* __restrict__ xdbl, const float* __restrict__ A2,
                        float* __restrict__ Ap, float* __restrict__ Be) {
    int t = blockIdx.x * blockDim.x + threadIdx.x;
    if (t >= NCHUNK * DI * DSTATE) return;
    int chunk = t >> 15;
    int r = t & 32767;
    int n = r >> 11;
    int d = r & (DI - 1);
    float a2 = A2[d * DSTATE + n];
    float h = 0.f, ap = 1.f;
    int l0 = chunk * CHUNKL;
    for (int s = 0; s < CHUNKL; ++s) {
        int l = l0 + s;
        float dtv = dt[(size_t)l * DI + d];
        float uv  = u [(size_t)l * DI + d];
        float bv  = xdbl[l * XDBL_W + DTRANK + n];
        float a = exp2f(dtv * a2);
        h = fmaf(a, h, dtv * uv * bv);
        ap *= a;
    }
    Ap[t] = ap;
    Be[t] = h;
}

// ---------------- scan pass 2: inter-chunk sequential scan ----------------
__global__ void scan2_k(const float* __restrict__ Ap, const float* __restrict__ Be,
                        float* __restrict__ hin) {
    int t = blockIdx.x * blockDim.x + threadIdx.x;
    if (t >= DI * DSTATE) return;
    float h = 0.f;
    #pragma unroll
    for (int c = 0; c < NCHUNK; ++c) {
        hin[c * (DI * DSTATE) + t] = h;
        h = fmaf(Ap[c * (DI * DSTATE) + t], h, Be[c * (DI * DSTATE) + t]);
    }
}

// ---------------- scan pass 3: recompute with h_in, fuse y, D-skip, gate ----------------
__global__ void scan3_k(const float* __restrict__ dt, const float* __restrict__ u,
                        const float* __restrict__ xdbl, const float* __restrict__ A2,
                        const float* __restrict__ hin, const float* __restrict__ Dp,
                        const float* __restrict__ xz, float* __restrict__ y) {
    int t = blockIdx.x * blockDim.x + threadIdx.x;
    if (t >= NCHUNK * DI) return;
    int chunk = t >> 11;
    int d = t & (DI - 1);
    float h[DSTATE], a2[DSTATE];
    #pragma unroll
    for (int n = 0; n < DSTATE; ++n) {
        h[n]  = hin[chunk * (DI * DSTATE) + n * DI + d];
        a2[n] = A2[d * DSTATE + n];
    }
    float Dd = Dp[d];
    int l0 = chunk * CHUNKL;
    for (int s = 0; s < CHUNKL; ++s) {
        int l = l0 + s;
        float dtv = dt[(size_t)l * DI + d];
        float uv  = u [(size_t)l * DI + d];
        float du  = dtv * uv;
        float acc = 0.f;
        #pragma unroll
        for (int n = 0; n < DSTATE; ++n) {
            float a = exp2f(dtv * a2[n]);
            h[n] = fmaf(a, h[n], du * xdbl[l * XDBL_W + DTRANK + n]);
            acc  = fmaf(h[n], xdbl[l * XDBL_W + DTRANK + DSTATE + n], acc);
        }
        acc = fmaf(uv, Dd, acc);
        float zv = xz[(size_t)l * (2 * DI) + DI + d];
        y[(size_t)l * DI + d] = acc * siluf(zv);
    }
}

// ---------------- avg pool 4x4 over (h,w) ----------------
__global__ void pool_k(const float* __restrict__ x, float* __restrict__ o) {
    int t = blockIdx.x * blockDim.x + threadIdx.x;
    if (t >= POOLED * DM) return;
    int d = t & (DM - 1);
    int po = t >> 10;
    int f = po >> 4, hh = (po >> 2) & 3, ww = po & 3;
    float s = 0.f;
    #pragma unroll
    for (int i = 0; i < 4; ++i)
        #pragma unroll
        for (int j = 0; j < 4; ++j) {
            int l = f * 256 + (hh * 4 + i) * 16 + (ww * 4 + j);
            s += x[(size_t)l * DM + d];
        }
    o[t] = s * 0.0625f;
}

// ---------------- launch ----------------
extern "C" void kernel_launch(void* const* d_in, const int* in_sizes, int n_in,
                              void* d_out, int out_size) {
    const float* vst        = (const float*)d_in[0];
    const float* ln_w       = (const float*)d_in[1];
    const float* ln_b       = (const float*)d_in[2];
    const float* in_proj_w  = (const float*)d_in[3];
    const float* conv_w     = (const float*)d_in[4];
    const float* conv_b     = (const float*)d_in[5];
    const float* x_proj_w   = (const float*)d_in[6];
    const float* dt_proj_w  = (const float*)d_in[7];
    const float* dt_proj_b  = (const float*)d_in[8];
    const float* A_log      = (const float*)d_in[9];
    const float* D_param    = (const float*)d_in[10];
    const float* out_proj_w = (const float*)d_in[11];
    const float* fln_w      = (const float*)d_in[12];
    const float* fln_b      = (const float*)d_in[13];
    const float* mlp_w1     = (const float*)d_in[14];
    const float* mlp_b1     = (const float*)d_in[15];
    const float* mlp_w2     = (const float*)d_in[16];
    const float* mlp_b2     = (const float*)d_in[17];
    float* out = (float*)d_out;

    float *p_ln, *p_xz, *p_u, *p_xdbl, *p_dt, *p_y, *p_mamba, *p_ln2,
          *p_pool, *p_mid, *p_A2, *p_Ap, *p_Be, *p_hin, *p_part;
    cudaGetSymbolAddress((void**)&p_ln,    g_ln);
    cudaGetSymbolAddress((void**)&p_xz,    g_xz);
    cudaGetSymbolAddress((void**)&p_u,     g_u);
    cudaGetSymbolAddress((void**)&p_xdbl,  g_xdbl);
    cudaGetSymbolAddress((void**)&p_dt,    g_dt);
    cudaGetSymbolAddress((void**)&p_y,     g_y);
    cudaGetSymbolAddress((void**)&p_mamba, g_mamba);
    cudaGetSymbolAddress((void**)&p_ln2,   g_ln2);
    cudaGetSymbolAddress((void**)&p_pool,  g_pool);
    cudaGetSymbolAddress((void**)&p_mid,   g_mid);
    cudaGetSymbolAddress((void**)&p_A2,    g_A2);
    cudaGetSymbolAddress((void**)&p_Ap,    g_Ap);
    cudaGetSymbolAddress((void**)&p_Be,    g_Be);
    cudaGetSymbolAddress((void**)&p_hin,   g_hin);
    cudaGetSymbolAddress((void**)&p_part,  g_part);

    cudaFuncSetAttribute(gemm_bf16x3_k<0>, cudaFuncAttributeMaxDynamicSharedMemorySize, SMEM_DYN_BYTES);
    cudaFuncSetAttribute(gemm_bf16x3_k<1>, cudaFuncAttributeMaxDynamicSharedMemorySize, SMEM_DYN_BYTES);
    cudaFuncSetAttribute(gemm_bf16x3_k<2>, cudaFuncAttributeMaxDynamicSharedMemorySize, SMEM_DYN_BYTES);

    // 1. layernorm
    layernorm_k<<<L_SEQ, 256>>>(vst, p_ln, ln_w, ln_b, DM);

    // 2. in_proj: [4096,1024] @ [1024,4096]
    gemm_bf16x3_k<0><<<dim3(32, 32, 1), 512, SMEM_DYN_BYTES>>>(
        p_ln, DM, in_proj_w, 2*DI, p_xz, 2*DI, nullptr, nullptr, nullptr, 0,
        L_SEQ, 2*DI, DM);

    // 3. depthwise conv + silu
    conv_silu_k<<<(L_SEQ * DI) / 256, 256>>>(p_xz, conv_w, conv_b, p_u);

    // 4. x_proj: [4096,2048] @ [2048,96], split-K=8
    gemm_bf16x3_k<0><<<dim3(1, 32, 8), 512, SMEM_DYN_BYTES>>>(
        p_u, DI, x_proj_w, XDBL_W, nullptr, 0, p_part, nullptr, nullptr, 0,
        L_SEQ, XDBL_W, DI);
    reduceK_k<0><<<(L_SEQ * XDBL_W / 4 + 255) / 256, 256>>>(
        p_part, 8, L_SEQ * XDBL_W, XDBL_W, nullptr, p_xdbl);

    // 5. dt_proj + softplus: [4096,64] @ [64,2048]
    gemm_bf16x3_k<1><<<dim3(16, 32, 1), 512, SMEM_DYN_BYTES>>>(
        p_xdbl, XDBL_W, dt_proj_w, DI, p_dt, DI, nullptr, dt_proj_b, nullptr, 0,
        L_SEQ, DI, DTRANK);

    // 6. selective scan (3-pass chunked)
    a2_k<<<(DI * DSTATE) / 256, 256>>>(A_log, p_A2);
    scan1_k<<<(NCHUNK * DI * DSTATE) / 256, 256>>>(p_dt, p_u, p_xdbl, p_A2, p_Ap, p_Be);
    scan2_k<<<(DI * DSTATE) / 256, 256>>>(p_Ap, p_Be, p_hin);
    scan3_k<<<(NCHUNK * DI) / 256, 256>>>(p_dt, p_u, p_xdbl, p_A2, p_hin, D_param, p_xz, p_y);

    // 7. out_proj + residual: [4096,2048] @ [2048,1024] + vst
    gemm_bf16x3_k<2><<<dim3(8, 32, 1), 512, SMEM_DYN_BYTES>>>(
        p_y, DI, out_proj_w, DM, p_mamba, DM, nullptr, nullptr, vst, DM,
        L_SEQ, DM, DI);

    // 8. final layernorm
    layernorm_k<<<L_SEQ, 256>>>(p_mamba, p_ln2, fln_w, fln_b, DM);

    // 9. avg pool 4x4
    pool_k<<<(POOLED * DM) / 256, 256>>>(p_ln2, p_pool);

    // 10. mlp1: [256,1024] @ [1024,4096], split-K=4, gelu+bias epilogue in reduce
    gemm_bf16x3_k<0><<<dim3(32, 2, 4), 512, SMEM_DYN_BYTES>>>(
        p_pool, DM, mlp_w1, HID, nullptr, 0, p_part, nullptr, nullptr, 0,
        POOLED, HID, DM);
    reduceK_k<3><<<(POOLED * HID / 4 + 255) / 256, 256>>>(
        p_part, 4, POOLED * HID, HID, mlp_b1, p_mid);

    // 11. mlp2: [256,4096] @ [4096,4096], split-K=8, bias epilogue in reduce
    gemm_bf16x3_k<0><<<dim3(32, 2, 8), 512, SMEM_DYN_BYTES>>>(
        p_mid, HID, mlp_w2, HID, nullptr, 0, p_part, nullptr, nullptr, 0,
        POOLED, HID, HID);
    reduceK_k<4><<<(POOLED * HID / 4 + 255) / 256, 256>>>(
        p_part, 8, POOLED * HID, HID, mlp_b2, out);
}